// round 9
// baseline (speedup 1.0000x reference)
#include <cuda_runtime.h>
#include <math.h>

// ChamferReward — R9: depth-1 software-pipelined LDS prefetch. R8's profile
// showed issue=40.7% with occupancy UP -> per-warp LDS->FMA chain exposure
// (~60 cyc/jp, no inter-jp overlap). Prefetch jp+1's B-operands before the
// FMA/min work on jp; register rotate. Same loads, same FMA order -> bit-
// identical results. bestc packed 4x6bit into one reg to stay under the
// 85-reg cap of launch_bounds(256,3).

#define N_PART  1024
#define NJP     512
#define THREADS 256
#define ITEMS   4
#define CJP     8               // jp per chunk (16 j)
#define NCHUNK  (NJP / CJP)     // 64
#define NCTA    1024

typedef unsigned long long ull;

__device__ float g_partials[NCTA];
__device__ unsigned int g_arrived = 0;

#define FMA2(d, a, b, c) \
    asm("fma.rn.f32x2 %0, %1, %2, %3;" : "=l"(d) : "l"(a), "l"(b), "l"(c))

__device__ __forceinline__ ull pack_dup(float x) {
    ull r;
    unsigned xi = __float_as_uint(x);
    asm("mov.b64 %0, {%1, %1};" : "=l"(r) : "r"(xi));
    return r;
}

__device__ __forceinline__ void unpack2(ull v, float& lo, float& hi) {
    unsigned a, b;
    asm("mov.b64 {%0, %1}, %2;" : "=r"(a), "=r"(b) : "l"(v));
    lo = __uint_as_float(a);
    hi = __uint_as_float(b);
}

__global__ void __launch_bounds__(THREADS, 3)
chamfer_pass_kernel(const float* __restrict__ achieved,
                    const float* __restrict__ desired,
                    const float* __restrict__ norm_mean,
                    const float* __restrict__ norm_std,
                    float* __restrict__ out)
{
    __shared__ ulonglong2 sb01[NJP];   // 8KB: {b0 pair, b1 pair}
    __shared__ ulonglong2 sb23[NJP];   // 8KB: {b2 pair, b3 pair}
    __shared__ ull        sbb[NJP];    // 4KB: |b|^2 pair
    __shared__ float2     sxy[N_PART]; // 8KB
    __shared__ float      warp_sums[THREADS / 32];
    __shared__ unsigned int s_rank;

    const int c    = blockIdx.x;
    const int pass = c & 1;
    const int bv   = c >> 1;

    const float* ownp;
    const float* strp;
    if (pass == 0) { ownp = desired;  strp = achieved; }
    else           { ownp = achieved; strp = desired;  }
    const size_t base = (size_t)bv * (size_t)N_PART * 10;
    ownp += base;
    strp += base;

    const float m0 = __ldg(norm_mean + 0), m1 = __ldg(norm_mean + 1);
    const float m5 = __ldg(norm_mean + 5), m6 = __ldg(norm_mean + 6);
    const float m7 = __ldg(norm_mean + 7), m8 = __ldg(norm_mean + 8);
    const float s0 = __ldg(norm_std  + 0), s1 = __ldg(norm_std  + 1);
    const float s5 = __ldg(norm_std  + 5), s6 = __ldg(norm_std  + 6);
    const float s7 = __ldg(norm_std  + 7), s8 = __ldg(norm_std  + 8);

    const int tid = threadIdx.x;

    // ---- Stage streamed side (normalize, precompute |vis|^2) ----
    {
        float* f01 = (float*)sb01;   // per jp: [b0_lo, b0_hi, b1_lo, b1_hi]
        float* f23 = (float*)sb23;   // per jp: [b2_lo, b2_hi, b3_lo, b3_hi]
        float* fbb = (float*)sbb;    // contiguous over j
        for (int i = tid; i < N_PART; i += THREADS) {
            const float2* r2 = (const float2*)(strp + i * 10);
            const float2 q0 = r2[0];   // r0, r1
            const float2 q1 = r2[2];   // r4, r5
            const float2 q2 = r2[3];   // r6, r7
            const float2 q3 = r2[4];   // r8, r9
            float x0 = fmaf(q0.x, s0, m0);
            float x1 = fmaf(q0.y, s1, m1);
            float v0 = fmaf(q1.y, s5, m5);
            float v1 = fmaf(q2.x, s6, m6);
            float v2 = fmaf(q2.y, s7, m7);
            float v3 = fmaf(q3.x, s8, m8);
            const int jp = i >> 1, h = i & 1;
            f01[jp * 4 + h]     = v0;
            f01[jp * 4 + 2 + h] = v1;
            f23[jp * 4 + h]     = v2;
            f23[jp * 4 + 2 + h] = v3;
            fbb[i] = v0 * v0 + v1 * v1 + v2 * v2 + v3 * v3;
            sxy[i] = make_float2(x0, x1);
        }
    }

    // ---- Owned items: a' = -2a, duplicated into both packed halves ----
    ull a0d[ITEMS], a1d[ITEMS], a2d[ITEMS], a3d[ITEMS];
#pragma unroll
    for (int k = 0; k < ITEMS; k++) {
        const int i = tid + k * THREADS;
        const float2* r2 = (const float2*)(ownp + i * 10);
        const float2 q1 = r2[2];
        const float2 q2 = r2[3];
        const float2 q3 = r2[4];
        float a0 = fmaf(q1.y, s5, m5);
        float a1 = fmaf(q2.x, s6, m6);
        float a2 = fmaf(q2.y, s7, m7);
        float a3 = fmaf(q3.x, s8, m8);
        a0d[k] = pack_dup(-2.0f * a0);
        a1d[k] = pack_dup(-2.0f * a1);
        a2d[k] = pack_dup(-2.0f * a2);
        a3d[k] = pack_dup(-2.0f * a3);
    }

    __syncthreads();

    // ---- Main loop: software-pipelined (depth-1 LDS prefetch) ----
    float bestd[ITEMS];
    unsigned bcp = 0;               // 4 x 6-bit packed chunk ids
#pragma unroll
    for (int k = 0; k < ITEMS; k++) bestd[k] = 3.4e38f;

    for (int ch = 0; ch < NCHUNK; ch++) {
        float cm[ITEMS];
#pragma unroll
        for (int k = 0; k < ITEMS; k++) cm[k] = 3.4e38f;

        const int jp0 = ch * CJP;
        ulonglong2 c01 = sb01[jp0];
        ulonglong2 c23 = sb23[jp0];
        ull        cac = sbb[jp0];

#pragma unroll
        for (int u = 0; u < CJP; u++) {
            ulonglong2 n01, n23;
            ull        nac;
            if (u < CJP - 1) {               // prefetch next jp before compute
                n01 = sb01[jp0 + u + 1];
                n23 = sb23[jp0 + u + 1];
                nac = sbb[jp0 + u + 1];
            }
#pragma unroll
            for (int k = 0; k < ITEMS; k++) {
                ull t;
                FMA2(t, a0d[k], c01.x, cac);
                FMA2(t, a1d[k], c01.y, t);
                FMA2(t, a2d[k], c23.x, t);
                FMA2(t, a3d[k], c23.y, t);
                float lo, hi;
                unpack2(t, lo, hi);                  // register-naming only
                cm[k] = fminf(cm[k], fminf(lo, hi)); // inner fmin not loop-carried
            }
            if (u < CJP - 1) { c01 = n01; c23 = n23; cac = nac; }
        }
#pragma unroll
        for (int k = 0; k < ITEMS; k++) {
            if (cm[k] < bestd[k]) {                  // strict <: first chunk wins
                bestd[k] = cm[k];
                bcp = (bcp & ~(63u << (k * 6))) | ((unsigned)ch << (k * 6));
            }
        }
    }

    // ---- Tail: recompute own xy/|a|^2 (bit-identical), rescan, sum ----
    float partial = 0.0f;
#pragma unroll
    for (int k = 0; k < ITEMS; k++) {
        const int i = tid + k * THREADS;
        const float2* r2 = (const float2*)(ownp + i * 10);
        const float2 q0 = r2[0];
        const float2 q1 = r2[2];
        const float2 q2 = r2[3];
        const float2 q3 = r2[4];
        const float ox = fmaf(q0.x, s0, m0);
        const float oy = fmaf(q0.y, s1, m1);
        const float a0 = fmaf(q1.y, s5, m5);
        const float a1 = fmaf(q2.x, s6, m6);
        const float a2 = fmaf(q2.y, s7, m7);
        const float a3 = fmaf(q3.x, s8, m8);
        const float aa = a0 * a0 + a1 * a1 + a2 * a2 + a3 * a3;

        const float bd = bestd[k];
        const int jp0 = (int)((bcp >> (k * 6)) & 63u) * CJP;
        int jbest = jp0 * 2;
        bool found = false;
        for (int u = 0; u < CJP; u++) {
            const int jp = jp0 + u;
            const ulonglong2 p01 = sb01[jp];
            const ulonglong2 p23 = sb23[jp];
            const ull        acc = sbb[jp];
            ull t;
            FMA2(t, a0d[k], p01.x, acc);
            FMA2(t, a1d[k], p01.y, t);
            FMA2(t, a2d[k], p23.x, t);
            FMA2(t, a3d[k], p23.y, t);
            float lo, hi;
            unpack2(t, lo, hi);
            if (!found && lo == bd) { jbest = jp * 2;     found = true; }
            if (!found && hi == bd) { jbest = jp * 2 + 1; found = true; }
        }

        const float2 p = sxy[jbest];
        const float dx = ox - p.x;
        const float dy = oy - p.y;
        float xd = sqrtf(dx * dx + dy * dy);
        const float min_d = aa + bd;        // true squared latent distance
        if (min_d > 6.0f) xd = 1.0f;        // LATENT_DIST_THRESHOLD
        partial += xd;
    }

    // ---- Block reduce (deterministic) ----
#pragma unroll
    for (int off = 16; off > 0; off >>= 1)
        partial += __shfl_down_sync(0xffffffffu, partial, off);
    if ((tid & 31) == 0) warp_sums[tid >> 5] = partial;
    __syncthreads();
    if (tid == 0) {
        float s = 0.0f;
#pragma unroll
        for (int w = 0; w < THREADS / 32; w++) s += warp_sums[w];
        g_partials[c] = s;
        __threadfence();
        s_rank = atomicAdd(&g_arrived, 1u);   // last CTA reduces
    }
    __syncthreads();

    if (s_rank == NCTA - 1) {
        __threadfence();                    // acquire partials
        if (tid < 128) {
            float s = 0.0f;
#pragma unroll
            for (int t = 0; t < 8; t++) s += g_partials[tid * 8 + t];
            out[tid] = -s * (1.0f / (1024.0f * 8.0f));
        }
        __syncthreads();
        if (tid == 0) g_arrived = 0;        // reset for next graph replay
    }
}

extern "C" void kernel_launch(void* const* d_in, const int* in_sizes, int n_in,
                              void* d_out, int out_size)
{
    const float* achieved  = (const float*)d_in[0];
    const float* desired   = (const float*)d_in[1];
    const float* norm_mean = (const float*)d_in[2];
    const float* norm_std  = (const float*)d_in[3];
    float* out = (float*)d_out;

    chamfer_pass_kernel<<<NCTA, THREADS>>>(achieved, desired, norm_mean, norm_std, out);
}

// round 10
// speedup vs baseline: 1.0016x; 1.0016x over previous
#include <cuda_runtime.h>
#include <math.h>

// ChamferReward — R9: depth-1 software-pipelined LDS prefetch. R8's profile
// showed issue=40.7% with occupancy UP -> per-warp LDS->FMA chain exposure
// (~60 cyc/jp, no inter-jp overlap). Prefetch jp+1's B-operands before the
// FMA/min work on jp; register rotate. Same loads, same FMA order -> bit-
// identical results. bestc packed 4x6bit into one reg to stay under the
// 85-reg cap of launch_bounds(256,3).

#define N_PART  1024
#define NJP     512
#define THREADS 256
#define ITEMS   4
#define CJP     8               // jp per chunk (16 j)
#define NCHUNK  (NJP / CJP)     // 64
#define NCTA    1024

typedef unsigned long long ull;

__device__ float g_partials[NCTA];
__device__ unsigned int g_arrived = 0;

#define FMA2(d, a, b, c) \
    asm("fma.rn.f32x2 %0, %1, %2, %3;" : "=l"(d) : "l"(a), "l"(b), "l"(c))

__device__ __forceinline__ ull pack_dup(float x) {
    ull r;
    unsigned xi = __float_as_uint(x);
    asm("mov.b64 %0, {%1, %1};" : "=l"(r) : "r"(xi));
    return r;
}

__device__ __forceinline__ void unpack2(ull v, float& lo, float& hi) {
    unsigned a, b;
    asm("mov.b64 {%0, %1}, %2;" : "=r"(a), "=r"(b) : "l"(v));
    lo = __uint_as_float(a);
    hi = __uint_as_float(b);
}

__global__ void __launch_bounds__(THREADS, 3)
chamfer_pass_kernel(const float* __restrict__ achieved,
                    const float* __restrict__ desired,
                    const float* __restrict__ norm_mean,
                    const float* __restrict__ norm_std,
                    float* __restrict__ out)
{
    __shared__ ulonglong2 sb01[NJP];   // 8KB: {b0 pair, b1 pair}
    __shared__ ulonglong2 sb23[NJP];   // 8KB: {b2 pair, b3 pair}
    __shared__ ull        sbb[NJP];    // 4KB: |b|^2 pair
    __shared__ float2     sxy[N_PART]; // 8KB
    __shared__ float      warp_sums[THREADS / 32];
    __shared__ unsigned int s_rank;

    const int c    = blockIdx.x;
    const int pass = c & 1;
    const int bv   = c >> 1;

    const float* ownp;
    const float* strp;
    if (pass == 0) { ownp = desired;  strp = achieved; }
    else           { ownp = achieved; strp = desired;  }
    const size_t base = (size_t)bv * (size_t)N_PART * 10;
    ownp += base;
    strp += base;

    const float m0 = __ldg(norm_mean + 0), m1 = __ldg(norm_mean + 1);
    const float m5 = __ldg(norm_mean + 5), m6 = __ldg(norm_mean + 6);
    const float m7 = __ldg(norm_mean + 7), m8 = __ldg(norm_mean + 8);
    const float s0 = __ldg(norm_std  + 0), s1 = __ldg(norm_std  + 1);
    const float s5 = __ldg(norm_std  + 5), s6 = __ldg(norm_std  + 6);
    const float s7 = __ldg(norm_std  + 7), s8 = __ldg(norm_std  + 8);

    const int tid = threadIdx.x;

    // ---- Stage streamed side (normalize, precompute |vis|^2) ----
    {
        float* f01 = (float*)sb01;   // per jp: [b0_lo, b0_hi, b1_lo, b1_hi]
        float* f23 = (float*)sb23;   // per jp: [b2_lo, b2_hi, b3_lo, b3_hi]
        float* fbb = (float*)sbb;    // contiguous over j
        for (int i = tid; i < N_PART; i += THREADS) {
            const float2* r2 = (const float2*)(strp + i * 10);
            const float2 q0 = r2[0];   // r0, r1
            const float2 q1 = r2[2];   // r4, r5
            const float2 q2 = r2[3];   // r6, r7
            const float2 q3 = r2[4];   // r8, r9
            float x0 = fmaf(q0.x, s0, m0);
            float x1 = fmaf(q0.y, s1, m1);
            float v0 = fmaf(q1.y, s5, m5);
            float v1 = fmaf(q2.x, s6, m6);
            float v2 = fmaf(q2.y, s7, m7);
            float v3 = fmaf(q3.x, s8, m8);
            const int jp = i >> 1, h = i & 1;
            f01[jp * 4 + h]     = v0;
            f01[jp * 4 + 2 + h] = v1;
            f23[jp * 4 + h]     = v2;
            f23[jp * 4 + 2 + h] = v3;
            fbb[i] = v0 * v0 + v1 * v1 + v2 * v2 + v3 * v3;
            sxy[i] = make_float2(x0, x1);
        }
    }

    // ---- Owned items: a' = -2a, duplicated into both packed halves ----
    ull a0d[ITEMS], a1d[ITEMS], a2d[ITEMS], a3d[ITEMS];
#pragma unroll
    for (int k = 0; k < ITEMS; k++) {
        const int i = tid + k * THREADS;
        const float2* r2 = (const float2*)(ownp + i * 10);
        const float2 q1 = r2[2];
        const float2 q2 = r2[3];
        const float2 q3 = r2[4];
        float a0 = fmaf(q1.y, s5, m5);
        float a1 = fmaf(q2.x, s6, m6);
        float a2 = fmaf(q2.y, s7, m7);
        float a3 = fmaf(q3.x, s8, m8);
        a0d[k] = pack_dup(-2.0f * a0);
        a1d[k] = pack_dup(-2.0f * a1);
        a2d[k] = pack_dup(-2.0f * a2);
        a3d[k] = pack_dup(-2.0f * a3);
    }

    __syncthreads();

    // ---- Main loop: software-pipelined (depth-1 LDS prefetch) ----
    float bestd[ITEMS];
    unsigned bcp = 0;               // 4 x 6-bit packed chunk ids
#pragma unroll
    for (int k = 0; k < ITEMS; k++) bestd[k] = 3.4e38f;

    for (int ch = 0; ch < NCHUNK; ch++) {
        float cm[ITEMS];
#pragma unroll
        for (int k = 0; k < ITEMS; k++) cm[k] = 3.4e38f;

        const int jp0 = ch * CJP;
        ulonglong2 c01 = sb01[jp0];
        ulonglong2 c23 = sb23[jp0];
        ull        cac = sbb[jp0];

#pragma unroll
        for (int u = 0; u < CJP; u++) {
            ulonglong2 n01, n23;
            ull        nac;
            if (u < CJP - 1) {               // prefetch next jp before compute
                n01 = sb01[jp0 + u + 1];
                n23 = sb23[jp0 + u + 1];
                nac = sbb[jp0 + u + 1];
            }
#pragma unroll
            for (int k = 0; k < ITEMS; k++) {
                ull t;
                FMA2(t, a0d[k], c01.x, cac);
                FMA2(t, a1d[k], c01.y, t);
                FMA2(t, a2d[k], c23.x, t);
                FMA2(t, a3d[k], c23.y, t);
                float lo, hi;
                unpack2(t, lo, hi);                  // register-naming only
                cm[k] = fminf(cm[k], fminf(lo, hi)); // inner fmin not loop-carried
            }
            if (u < CJP - 1) { c01 = n01; c23 = n23; cac = nac; }
        }
#pragma unroll
        for (int k = 0; k < ITEMS; k++) {
            if (cm[k] < bestd[k]) {                  // strict <: first chunk wins
                bestd[k] = cm[k];
                bcp = (bcp & ~(63u << (k * 6))) | ((unsigned)ch << (k * 6));
            }
        }
    }

    // ---- Tail: recompute own xy/|a|^2 (bit-identical), rescan, sum ----
    float partial = 0.0f;
#pragma unroll
    for (int k = 0; k < ITEMS; k++) {
        const int i = tid + k * THREADS;
        const float2* r2 = (const float2*)(ownp + i * 10);
        const float2 q0 = r2[0];
        const float2 q1 = r2[2];
        const float2 q2 = r2[3];
        const float2 q3 = r2[4];
        const float ox = fmaf(q0.x, s0, m0);
        const float oy = fmaf(q0.y, s1, m1);
        const float a0 = fmaf(q1.y, s5, m5);
        const float a1 = fmaf(q2.x, s6, m6);
        const float a2 = fmaf(q2.y, s7, m7);
        const float a3 = fmaf(q3.x, s8, m8);
        const float aa = a0 * a0 + a1 * a1 + a2 * a2 + a3 * a3;

        const float bd = bestd[k];
        const int jp0 = (int)((bcp >> (k * 6)) & 63u) * CJP;
        int jbest = jp0 * 2;
        bool found = false;
        for (int u = 0; u < CJP; u++) {
            const int jp = jp0 + u;
            const ulonglong2 p01 = sb01[jp];
            const ulonglong2 p23 = sb23[jp];
            const ull        acc = sbb[jp];
            ull t;
            FMA2(t, a0d[k], p01.x, acc);
            FMA2(t, a1d[k], p01.y, t);
            FMA2(t, a2d[k], p23.x, t);
            FMA2(t, a3d[k], p23.y, t);
            float lo, hi;
            unpack2(t, lo, hi);
            if (!found && lo == bd) { jbest = jp * 2;     found = true; }
            if (!found && hi == bd) { jbest = jp * 2 + 1; found = true; }
        }

        const float2 p = sxy[jbest];
        const float dx = ox - p.x;
        const float dy = oy - p.y;
        float xd = sqrtf(dx * dx + dy * dy);
        const float min_d = aa + bd;        // true squared latent distance
        if (min_d > 6.0f) xd = 1.0f;        // LATENT_DIST_THRESHOLD
        partial += xd;
    }

    // ---- Block reduce (deterministic) ----
#pragma unroll
    for (int off = 16; off > 0; off >>= 1)
        partial += __shfl_down_sync(0xffffffffu, partial, off);
    if ((tid & 31) == 0) warp_sums[tid >> 5] = partial;
    __syncthreads();
    if (tid == 0) {
        float s = 0.0f;
#pragma unroll
        for (int w = 0; w < THREADS / 32; w++) s += warp_sums[w];
        g_partials[c] = s;
        __threadfence();
        s_rank = atomicAdd(&g_arrived, 1u);   // last CTA reduces
    }
    __syncthreads();

    if (s_rank == NCTA - 1) {
        __threadfence();                    // acquire partials
        if (tid < 128) {
            float s = 0.0f;
#pragma unroll
            for (int t = 0; t < 8; t++) s += g_partials[tid * 8 + t];
            out[tid] = -s * (1.0f / (1024.0f * 8.0f));
        }
        __syncthreads();
        if (tid == 0) g_arrived = 0;        // reset for next graph replay
    }
}

extern "C" void kernel_launch(void* const* d_in, const int* in_sizes, int n_in,
                              void* d_out, int out_size)
{
    const float* achieved  = (const float*)d_in[0];
    const float* desired   = (const float*)d_in[1];
    const float* norm_mean = (const float*)d_in[2];
    const float* norm_std  = (const float*)d_in[3];
    float* out = (float*)d_out;

    chamfer_pass_kernel<<<NCTA, THREADS>>>(achieved, desired, norm_mean, norm_std, out);
}

// round 11
// speedup vs baseline: 1.0037x; 1.0021x over previous
#include <cuda_runtime.h>
#include <math.h>

// ChamferReward — R10: whole-chunk register hoist. Evidence: warps 4->6 and
// source prefetch both left issue at ~41% -> static LDS/FMA interleave is the
// limiter. Per 8-jp chunk: batch-load all B operands into a 40-reg array
// (forced by full unroll), then a pure FMA2/FMNMX burst with no memory deps.
// 2 CTAs/SM (128-reg budget). Math/order bit-identical to R8 champion.

#define N_PART  1024
#define NJP     512
#define THREADS 256
#define ITEMS   4
#define CJP     8               // jp per chunk (16 j)
#define NCHUNK  (NJP / CJP)     // 64
#define NCTA    1024

typedef unsigned long long ull;

__device__ float g_partials[NCTA];
__device__ unsigned int g_arrived = 0;

#define FMA2(d, a, b, c) \
    asm("fma.rn.f32x2 %0, %1, %2, %3;" : "=l"(d) : "l"(a), "l"(b), "l"(c))

__device__ __forceinline__ ull pack_dup(float x) {
    ull r;
    unsigned xi = __float_as_uint(x);
    asm("mov.b64 %0, {%1, %1};" : "=l"(r) : "r"(xi));
    return r;
}

__device__ __forceinline__ void unpack2(ull v, float& lo, float& hi) {
    unsigned a, b;
    asm("mov.b64 {%0, %1}, %2;" : "=r"(a), "=r"(b) : "l"(v));
    lo = __uint_as_float(a);
    hi = __uint_as_float(b);
}

__global__ void __launch_bounds__(THREADS, 2)
chamfer_pass_kernel(const float* __restrict__ achieved,
                    const float* __restrict__ desired,
                    const float* __restrict__ norm_mean,
                    const float* __restrict__ norm_std,
                    float* __restrict__ out)
{
    __shared__ ulonglong2 sb01[NJP];   // 8KB: {b0 pair, b1 pair}
    __shared__ ulonglong2 sb23[NJP];   // 8KB: {b2 pair, b3 pair}
    __shared__ ull        sbb[NJP];    // 4KB: |b|^2 pair
    __shared__ float2     sxy[N_PART]; // 8KB
    __shared__ float      warp_sums[THREADS / 32];
    __shared__ unsigned int s_rank;

    const int c    = blockIdx.x;
    const int pass = c & 1;
    const int bv   = c >> 1;

    const float* ownp;
    const float* strp;
    if (pass == 0) { ownp = desired;  strp = achieved; }
    else           { ownp = achieved; strp = desired;  }
    const size_t base = (size_t)bv * (size_t)N_PART * 10;
    ownp += base;
    strp += base;

    const float m0 = __ldg(norm_mean + 0), m1 = __ldg(norm_mean + 1);
    const float m5 = __ldg(norm_mean + 5), m6 = __ldg(norm_mean + 6);
    const float m7 = __ldg(norm_mean + 7), m8 = __ldg(norm_mean + 8);
    const float s0 = __ldg(norm_std  + 0), s1 = __ldg(norm_std  + 1);
    const float s5 = __ldg(norm_std  + 5), s6 = __ldg(norm_std  + 6);
    const float s7 = __ldg(norm_std  + 7), s8 = __ldg(norm_std  + 8);

    const int tid = threadIdx.x;

    // ---- Stage streamed side (normalize, precompute |vis|^2) ----
    {
        float* f01 = (float*)sb01;   // per jp: [b0_lo, b0_hi, b1_lo, b1_hi]
        float* f23 = (float*)sb23;   // per jp: [b2_lo, b2_hi, b3_lo, b3_hi]
        float* fbb = (float*)sbb;    // contiguous over j
        for (int i = tid; i < N_PART; i += THREADS) {
            const float2* r2 = (const float2*)(strp + i * 10);
            const float2 q0 = r2[0];   // r0, r1
            const float2 q1 = r2[2];   // r4, r5
            const float2 q2 = r2[3];   // r6, r7
            const float2 q3 = r2[4];   // r8, r9
            float x0 = fmaf(q0.x, s0, m0);
            float x1 = fmaf(q0.y, s1, m1);
            float v0 = fmaf(q1.y, s5, m5);
            float v1 = fmaf(q2.x, s6, m6);
            float v2 = fmaf(q2.y, s7, m7);
            float v3 = fmaf(q3.x, s8, m8);
            const int jp = i >> 1, h = i & 1;
            f01[jp * 4 + h]     = v0;
            f01[jp * 4 + 2 + h] = v1;
            f23[jp * 4 + h]     = v2;
            f23[jp * 4 + 2 + h] = v3;
            fbb[i] = v0 * v0 + v1 * v1 + v2 * v2 + v3 * v3;
            sxy[i] = make_float2(x0, x1);
        }
    }

    // ---- Owned items: a' = -2a, duplicated into both packed halves ----
    ull a0d[ITEMS], a1d[ITEMS], a2d[ITEMS], a3d[ITEMS];
#pragma unroll
    for (int k = 0; k < ITEMS; k++) {
        const int i = tid + k * THREADS;
        const float2* r2 = (const float2*)(ownp + i * 10);
        const float2 q1 = r2[2];
        const float2 q2 = r2[3];
        const float2 q3 = r2[4];
        float a0 = fmaf(q1.y, s5, m5);
        float a1 = fmaf(q2.x, s6, m6);
        float a2 = fmaf(q2.y, s7, m7);
        float a3 = fmaf(q3.x, s8, m8);
        a0d[k] = pack_dup(-2.0f * a0);
        a1d[k] = pack_dup(-2.0f * a1);
        a2d[k] = pack_dup(-2.0f * a2);
        a3d[k] = pack_dup(-2.0f * a3);
    }

    __syncthreads();

    // ---- Main loop: whole-chunk B hoist into registers, then FMA burst ----
    float bestd[ITEMS];
    unsigned bcp = 0;               // 4 x 6-bit packed chunk ids
#pragma unroll
    for (int k = 0; k < ITEMS; k++) bestd[k] = 3.4e38f;

    for (int ch = 0; ch < NCHUNK; ch++) {
        const int jp0 = ch * CJP;

        // Batch-load the whole chunk's B operands to registers (40 regs).
        ull B0[CJP], B1[CJP], B2[CJP], B3[CJP], BB[CJP];
#pragma unroll
        for (int u = 0; u < CJP; u++) {
            const ulonglong2 p01 = sb01[jp0 + u];
            const ulonglong2 p23 = sb23[jp0 + u];
            B0[u] = p01.x;
            B1[u] = p01.y;
            B2[u] = p23.x;
            B3[u] = p23.y;
            BB[u] = sbb[jp0 + u];
        }

        float cm[ITEMS];
#pragma unroll
        for (int k = 0; k < ITEMS; k++) cm[k] = 3.4e38f;

#pragma unroll
        for (int u = 0; u < CJP; u++) {
#pragma unroll
            for (int k = 0; k < ITEMS; k++) {
                ull t;
                FMA2(t, a0d[k], B0[u], BB[u]);
                FMA2(t, a1d[k], B1[u], t);
                FMA2(t, a2d[k], B2[u], t);
                FMA2(t, a3d[k], B3[u], t);
                float lo, hi;
                unpack2(t, lo, hi);                  // register-naming only
                cm[k] = fminf(cm[k], fminf(lo, hi)); // inner fmin not loop-carried
            }
        }
#pragma unroll
        for (int k = 0; k < ITEMS; k++) {
            if (cm[k] < bestd[k]) {                  // strict <: first chunk wins
                bestd[k] = cm[k];
                bcp = (bcp & ~(63u << (k * 6))) | ((unsigned)ch << (k * 6));
            }
        }
    }

    // ---- Tail: recompute own xy/|a|^2 (bit-identical), rescan, sum ----
    float partial = 0.0f;
#pragma unroll
    for (int k = 0; k < ITEMS; k++) {
        const int i = tid + k * THREADS;
        const float2* r2 = (const float2*)(ownp + i * 10);
        const float2 q0 = r2[0];
        const float2 q1 = r2[2];
        const float2 q2 = r2[3];
        const float2 q3 = r2[4];
        const float ox = fmaf(q0.x, s0, m0);
        const float oy = fmaf(q0.y, s1, m1);
        const float a0 = fmaf(q1.y, s5, m5);
        const float a1 = fmaf(q2.x, s6, m6);
        const float a2 = fmaf(q2.y, s7, m7);
        const float a3 = fmaf(q3.x, s8, m8);
        const float aa = a0 * a0 + a1 * a1 + a2 * a2 + a3 * a3;

        const float bd = bestd[k];
        const int jp0 = (int)((bcp >> (k * 6)) & 63u) * CJP;
        int jbest = jp0 * 2;
        bool found = false;
        for (int u = 0; u < CJP; u++) {
            const int jp = jp0 + u;
            const ulonglong2 p01 = sb01[jp];
            const ulonglong2 p23 = sb23[jp];
            const ull        acc = sbb[jp];
            ull t;
            FMA2(t, a0d[k], p01.x, acc);
            FMA2(t, a1d[k], p01.y, t);
            FMA2(t, a2d[k], p23.x, t);
            FMA2(t, a3d[k], p23.y, t);
            float lo, hi;
            unpack2(t, lo, hi);
            if (!found && lo == bd) { jbest = jp * 2;     found = true; }
            if (!found && hi == bd) { jbest = jp * 2 + 1; found = true; }
        }

        const float2 p = sxy[jbest];
        const float dx = ox - p.x;
        const float dy = oy - p.y;
        float xd = sqrtf(dx * dx + dy * dy);
        const float min_d = aa + bd;        // true squared latent distance
        if (min_d > 6.0f) xd = 1.0f;        // LATENT_DIST_THRESHOLD
        partial += xd;
    }

    // ---- Block reduce (deterministic) ----
#pragma unroll
    for (int off = 16; off > 0; off >>= 1)
        partial += __shfl_down_sync(0xffffffffu, partial, off);
    if ((tid & 31) == 0) warp_sums[tid >> 5] = partial;
    __syncthreads();
    if (tid == 0) {
        float s = 0.0f;
#pragma unroll
        for (int w = 0; w < THREADS / 32; w++) s += warp_sums[w];
        g_partials[c] = s;
        __threadfence();
        s_rank = atomicAdd(&g_arrived, 1u);   // last CTA reduces
    }
    __syncthreads();

    if (s_rank == NCTA - 1) {
        __threadfence();                    // acquire partials
        if (tid < 128) {
            float s = 0.0f;
#pragma unroll
            for (int t = 0; t < 8; t++) s += g_partials[tid * 8 + t];
            out[tid] = -s * (1.0f / (1024.0f * 8.0f));
        }
        __syncthreads();
        if (tid == 0) g_arrived = 0;        // reset for next graph replay
    }
}

extern "C" void kernel_launch(void* const* d_in, const int* in_sizes, int n_in,
                              void* d_out, int out_size)
{
    const float* achieved  = (const float*)d_in[0];
    const float* desired   = (const float*)d_in[1];
    const float* norm_mean = (const float*)d_in[2];
    const float* norm_std  = (const float*)d_in[3];
    float* out = (float*)d_out;

    chamfer_pass_kernel<<<NCTA, THREADS>>>(achieved, desired, norm_mean, norm_std, out);
}

// round 12
// speedup vs baseline: 1.0831x; 1.0790x over previous
#include <cuda_runtime.h>
#include <math.h>

// ChamferReward — R11: LDS-traffic diet. Evidence: issue pinned at ~41% across
// occupancy/prefetch/hoist changes; fma=46% matches full-rate FMA2 at half
// duty; L1=55% matches non-dedup'd broadcast LDS (4 wf per uniform LDS.128).
// -> shared L1tex queue is the limiter. Fix: THREADS=128, ITEMS=8: per jp a
// warp now runs 32 FMA2 + 16 FMNMX per 3 LDS — smem bytes per FLOP halved.
// Math, FMA order, chunk fold, rescan: bit-identical to the R8 champion.

#define N_PART  1024
#define NJP     512
#define THREADS 128
#define ITEMS   8
#define CJP     8               // jp per chunk (16 j)
#define NCHUNK  (NJP / CJP)     // 64
#define NCTA    1024

typedef unsigned long long ull;

__device__ float g_partials[NCTA];
__device__ unsigned int g_arrived = 0;

#define FMA2(d, a, b, c) \
    asm("fma.rn.f32x2 %0, %1, %2, %3;" : "=l"(d) : "l"(a), "l"(b), "l"(c))

__device__ __forceinline__ ull pack_dup(float x) {
    ull r;
    unsigned xi = __float_as_uint(x);
    asm("mov.b64 %0, {%1, %1};" : "=l"(r) : "r"(xi));
    return r;
}

__device__ __forceinline__ void unpack2(ull v, float& lo, float& hi) {
    unsigned a, b;
    asm("mov.b64 {%0, %1}, %2;" : "=r"(a), "=r"(b) : "l"(v));
    lo = __uint_as_float(a);
    hi = __uint_as_float(b);
}

__global__ void __launch_bounds__(THREADS, 4)
chamfer_pass_kernel(const float* __restrict__ achieved,
                    const float* __restrict__ desired,
                    const float* __restrict__ norm_mean,
                    const float* __restrict__ norm_std,
                    float* __restrict__ out)
{
    __shared__ ulonglong2 sb01[NJP];   // 8KB: {b0 pair, b1 pair}
    __shared__ ulonglong2 sb23[NJP];   // 8KB: {b2 pair, b3 pair}
    __shared__ ull        sbb[NJP];    // 4KB: |b|^2 pair
    __shared__ float2     sxy[N_PART]; // 8KB
    __shared__ float      warp_sums[THREADS / 32];
    __shared__ unsigned int s_rank;

    const int c    = blockIdx.x;
    const int pass = c & 1;
    const int bv   = c >> 1;

    const float* ownp;
    const float* strp;
    if (pass == 0) { ownp = desired;  strp = achieved; }
    else           { ownp = achieved; strp = desired;  }
    const size_t base = (size_t)bv * (size_t)N_PART * 10;
    ownp += base;
    strp += base;

    const float m0 = __ldg(norm_mean + 0), m1 = __ldg(norm_mean + 1);
    const float m5 = __ldg(norm_mean + 5), m6 = __ldg(norm_mean + 6);
    const float m7 = __ldg(norm_mean + 7), m8 = __ldg(norm_mean + 8);
    const float s0 = __ldg(norm_std  + 0), s1 = __ldg(norm_std  + 1);
    const float s5 = __ldg(norm_std  + 5), s6 = __ldg(norm_std  + 6);
    const float s7 = __ldg(norm_std  + 7), s8 = __ldg(norm_std  + 8);

    const int tid = threadIdx.x;

    // ---- Stage streamed side (normalize, precompute |vis|^2) ----
    {
        float* f01 = (float*)sb01;   // per jp: [b0_lo, b0_hi, b1_lo, b1_hi]
        float* f23 = (float*)sb23;   // per jp: [b2_lo, b2_hi, b3_lo, b3_hi]
        float* fbb = (float*)sbb;    // contiguous over j
        for (int i = tid; i < N_PART; i += THREADS) {
            const float2* r2 = (const float2*)(strp + i * 10);
            const float2 q0 = r2[0];   // r0, r1
            const float2 q1 = r2[2];   // r4, r5
            const float2 q2 = r2[3];   // r6, r7
            const float2 q3 = r2[4];   // r8, r9
            float x0 = fmaf(q0.x, s0, m0);
            float x1 = fmaf(q0.y, s1, m1);
            float v0 = fmaf(q1.y, s5, m5);
            float v1 = fmaf(q2.x, s6, m6);
            float v2 = fmaf(q2.y, s7, m7);
            float v3 = fmaf(q3.x, s8, m8);
            const int jp = i >> 1, h = i & 1;
            f01[jp * 4 + h]     = v0;
            f01[jp * 4 + 2 + h] = v1;
            f23[jp * 4 + h]     = v2;
            f23[jp * 4 + 2 + h] = v3;
            fbb[i] = v0 * v0 + v1 * v1 + v2 * v2 + v3 * v3;
            sxy[i] = make_float2(x0, x1);
        }
    }

    // ---- Owned items: a' = -2a, duplicated into both packed halves ----
    ull a0d[ITEMS], a1d[ITEMS], a2d[ITEMS], a3d[ITEMS];
#pragma unroll
    for (int k = 0; k < ITEMS; k++) {
        const int i = tid + k * THREADS;
        const float2* r2 = (const float2*)(ownp + i * 10);
        const float2 q1 = r2[2];
        const float2 q2 = r2[3];
        const float2 q3 = r2[4];
        float a0 = fmaf(q1.y, s5, m5);
        float a1 = fmaf(q2.x, s6, m6);
        float a2 = fmaf(q2.y, s7, m7);
        float a3 = fmaf(q3.x, s8, m8);
        a0d[k] = pack_dup(-2.0f * a0);
        a1d[k] = pack_dup(-2.0f * a1);
        a2d[k] = pack_dup(-2.0f * a2);
        a3d[k] = pack_dup(-2.0f * a3);
    }

    __syncthreads();

    // ---- Main loop: single-chain value-only chunk minima ----
    float bestd[ITEMS];
    ull bcp = 0;                    // 8 x 6-bit packed chunk ids
#pragma unroll
    for (int k = 0; k < ITEMS; k++) bestd[k] = 3.4e38f;

    for (int ch = 0; ch < NCHUNK; ch++) {
        float cm[ITEMS];
#pragma unroll
        for (int k = 0; k < ITEMS; k++) cm[k] = 3.4e38f;

#pragma unroll
        for (int u = 0; u < CJP; u++) {
            const int jp = ch * CJP + u;
            const ulonglong2 p01 = sb01[jp];
            const ulonglong2 p23 = sb23[jp];
            const ull        acc = sbb[jp];
#pragma unroll
            for (int k = 0; k < ITEMS; k++) {
                ull t;
                FMA2(t, a0d[k], p01.x, acc);
                FMA2(t, a1d[k], p01.y, t);
                FMA2(t, a2d[k], p23.x, t);
                FMA2(t, a3d[k], p23.y, t);
                float lo, hi;
                unpack2(t, lo, hi);                  // register-naming only
                cm[k] = fminf(cm[k], fminf(lo, hi)); // inner fmin not loop-carried
            }
        }
#pragma unroll
        for (int k = 0; k < ITEMS; k++) {
            if (cm[k] < bestd[k]) {                  // strict <: first chunk wins
                bestd[k] = cm[k];
                bcp = (bcp & ~(63ull << (k * 6))) | ((ull)(unsigned)ch << (k * 6));
            }
        }
    }

    // ---- Tail: recompute own xy/|a|^2 (bit-identical), rescan, sum ----
    float partial = 0.0f;
#pragma unroll
    for (int k = 0; k < ITEMS; k++) {
        const int i = tid + k * THREADS;
        const float2* r2 = (const float2*)(ownp + i * 10);
        const float2 q0 = r2[0];
        const float2 q1 = r2[2];
        const float2 q2 = r2[3];
        const float2 q3 = r2[4];
        const float ox = fmaf(q0.x, s0, m0);
        const float oy = fmaf(q0.y, s1, m1);
        const float a0 = fmaf(q1.y, s5, m5);
        const float a1 = fmaf(q2.x, s6, m6);
        const float a2 = fmaf(q2.y, s7, m7);
        const float a3 = fmaf(q3.x, s8, m8);
        const float aa = a0 * a0 + a1 * a1 + a2 * a2 + a3 * a3;

        const float bd = bestd[k];
        const int jp0 = (int)((bcp >> (k * 6)) & 63ull) * CJP;
        int jbest = jp0 * 2;
        bool found = false;
        for (int u = 0; u < CJP; u++) {
            const int jp = jp0 + u;
            const ulonglong2 p01 = sb01[jp];
            const ulonglong2 p23 = sb23[jp];
            const ull        acc = sbb[jp];
            ull t;
            FMA2(t, a0d[k], p01.x, acc);
            FMA2(t, a1d[k], p01.y, t);
            FMA2(t, a2d[k], p23.x, t);
            FMA2(t, a3d[k], p23.y, t);
            float lo, hi;
            unpack2(t, lo, hi);
            if (!found && lo == bd) { jbest = jp * 2;     found = true; }
            if (!found && hi == bd) { jbest = jp * 2 + 1; found = true; }
        }

        const float2 p = sxy[jbest];
        const float dx = ox - p.x;
        const float dy = oy - p.y;
        float xd = sqrtf(dx * dx + dy * dy);
        const float min_d = aa + bd;        // true squared latent distance
        if (min_d > 6.0f) xd = 1.0f;        // LATENT_DIST_THRESHOLD
        partial += xd;
    }

    // ---- Block reduce (deterministic) ----
#pragma unroll
    for (int off = 16; off > 0; off >>= 1)
        partial += __shfl_down_sync(0xffffffffu, partial, off);
    if ((tid & 31) == 0) warp_sums[tid >> 5] = partial;
    __syncthreads();
    if (tid == 0) {
        float s = 0.0f;
#pragma unroll
        for (int w = 0; w < THREADS / 32; w++) s += warp_sums[w];
        g_partials[c] = s;
        __threadfence();
        s_rank = atomicAdd(&g_arrived, 1u);   // last CTA reduces
    }
    __syncthreads();

    if (s_rank == NCTA - 1) {
        __threadfence();                    // acquire partials
        // THREADS==128: every thread reduces one batch element.
        {
            float s = 0.0f;
#pragma unroll
            for (int t = 0; t < 8; t++) s += g_partials[tid * 8 + t];
            out[tid] = -s * (1.0f / (1024.0f * 8.0f));
        }
        __syncthreads();
        if (tid == 0) g_arrived = 0;        // reset for next graph replay
    }
}

extern "C" void kernel_launch(void* const* d_in, const int* in_sizes, int n_in,
                              void* d_out, int out_size)
{
    const float* achieved  = (const float*)d_in[0];
    const float* desired   = (const float*)d_in[1];
    const float* norm_mean = (const float*)d_in[2];
    const float* norm_std  = (const float*)d_in[3];
    float* out = (float*)d_out;

    chamfer_pass_kernel<<<NCTA, THREADS>>>(achieved, desired, norm_mean, norm_std, out);
}